// round 11
// baseline (speedup 1.0000x reference)
#include <cuda_runtime.h>
#include <cstdint>

#define HH 512
#define WW 512
#define NB 16
#define NPIX (HH*WW)
#define RB 16
#define MB (HH/RB)        // 32
#define FULL 0xffffffffu

static __device__ float g_d[NB*NPIX];             // A1-local rows, then pass-1 final
static __device__ float g_d2[NB*NPIX];            // A2-local rows (pass-2 band layout)
static __device__ unsigned char g_bmask[NB*NPIX]; // bit0 boundary, bit1 target
static __device__ int g_mxi[NB];
static __device__ float g_lr1[NB*MB*WW], g_bn1[NB*MB*WW];
static __device__ float g_lr2[NB*MB*WW], g_bn2[NB*MB*WW];
static __device__ double g_acc[2 + 4*NB];

// ---------------------------------------------------------------------------
// One chamfer row-step: 128 threads / 4 warps, 4 cols/thread, 8 shfls, 1 bar.
__device__ __forceinline__ void row_step(
    float v0, float v1, float v2, float v3,
    float& p0, float& p1, float& p2, float& p3, float& hl, float& hr,
    float aj0, float aj1, float aj2, float aj3, float ajL, float ajR,
    int lane, int w, int par,
    float (*sm_lb)[4], float (*sm_rb)[4])
{
    const float A = 0.955f, Bd = 1.3693f, INF = 1.0e6f;
    float s0 = fminf(fminf(v0, p0 + A), fminf(hl + Bd, p1 + Bd)) - aj0;
    float s1 = fminf(fminf(v1, p1 + A), fminf(p0 + Bd, p2 + Bd)) - aj1;
    float s2 = fminf(fminf(v2, p2 + A), fminf(p1 + Bd, p3 + Bd)) - aj2;
    float s3 = fminf(fminf(v3, p3 + A), fminf(p2 + Bd, hr + Bd)) - aj3;

    float run1 = fminf(s0, s1);
    float run2 = fminf(run1, s2);
    float run3 = fminf(run2, s3);

    float x = __shfl_up_sync(FULL, run3, 1);
    if (lane == 0) x = INF;
    #pragma unroll
    for (int o = 1; o < 32; o <<= 1)
        x = fminf(x, __shfl_up_sync(FULL, x, o));

    if (lane == 31) sm_lb[par][w] = fminf(run3, x);
    if (lane == 0)  sm_rb[par][w] = s0;
    __syncthreads();

    float t0s = sm_lb[par][0], t1s = sm_lb[par][1], t2s = sm_lb[par][2];
    float offw = INF;
    if (w > 0) offw = t0s;
    if (w > 1) offw = fminf(offw, t1s);
    if (w > 2) offw = fminf(offw, t2s);
    float xf = fminf(x, offw);

    float c0 = aj0 + fminf(s0,  xf);
    float c1 = aj1 + fminf(run1, xf);
    float c2 = aj2 + fminf(run2, xf);
    float c3 = aj3 + fminf(run3, xf);

    float nhl = __shfl_up_sync(FULL, c3, 1);
    float nhr = __shfl_down_sync(FULL, c0, 1);
    if (lane == 0) {
        if (w == 0) nhl = INF;
        else {
            float offm = INF;
            if (w - 1 > 0) offm = t0s;
            if (w - 1 > 1) offm = fminf(offm, t1s);
            nhl = ajL + fminf(sm_lb[par][w-1], offm);
        }
    }
    if (lane == 31) {
        if (w == 3) nhr = INF;
        else {
            float own = fminf(run3, x);
            nhr = ajR + fminf(sm_rb[par][w+1], fminf(own, offw));
        }
    }
    hl = nhl; hr = nhr;
    p0 = c0; p1 = c1; p2 = c2; p3 = c3;
}

__device__ __forceinline__ void load_init(const float* br, int q0, int lane,
                                          float& p0, float& p1, float& p2, float& p3,
                                          float& hl, float& hr)
{
    const float INF = 1.0e6f;
    float4 pv = *reinterpret_cast<const float4*>(br + q0);
    p0 = pv.x; p1 = pv.y; p2 = pv.z; p3 = pv.w;
    float sl = __shfl_up_sync(FULL, p3, 1);
    float sr = __shfl_down_sync(FULL, p0, 1);
    hl = (q0 == 0) ? INF : ((lane == 0) ? br[q0-1] : sl);
    hr = (q0 + 4 >= WW) ? INF : ((lane == 31) ? br[q0+4] : sr);
}

// ---------------------------------------------------------------------------
// Small-t conv tables from a boundary row (or INF if br==null):
// sPref1 (prefix of b-Aj), sPref2 (prefix of b-BAj), sSuf3 (suffix of b+BAj),
// sT2/sT3 sparse-table levels 0..4 (window widths up to 17).
__device__ __forceinline__ void build_ktab(const float* br, int q0, int lane, int w,
    float* sPref1, float* sPref2, float* sSuf3,
    float (*sT2)[512], float (*sT3)[512], float* wtmp)
{
    const float A = 0.955f, BA = 1.3693f - 0.955f, INF = 1.0e6f;
    float bv[4];
    if (br) {
        float4 t4 = *reinterpret_cast<const float4*>(br + q0);
        bv[0]=t4.x; bv[1]=t4.y; bv[2]=t4.z; bv[3]=t4.w;
    } else { bv[0]=bv[1]=bv[2]=bv[3]=INF; }
    float z1[4], z2[4], z3[4];
    #pragma unroll
    for (int c = 0; c < 4; c++) {
        float jf = (float)(q0 + c);
        z1[c] = bv[c] - A * jf;
        z2[c] = bv[c] - BA * jf;
        z3[c] = bv[c] + BA * jf;
    }
    *reinterpret_cast<float4*>(&sT2[0][q0]) = make_float4(z2[0],z2[1],z2[2],z2[3]);
    *reinterpret_cast<float4*>(&sT3[0][q0]) = make_float4(z3[0],z3[1],z3[2],z3[3]);

    float a1[4], a2[4], s3[4];
    a1[0]=z1[0]; a1[1]=fminf(a1[0],z1[1]); a1[2]=fminf(a1[1],z1[2]); a1[3]=fminf(a1[2],z1[3]);
    a2[0]=z2[0]; a2[1]=fminf(a2[0],z2[1]); a2[2]=fminf(a2[1],z2[2]); a2[3]=fminf(a2[2],z2[3]);
    s3[3]=z3[3]; s3[2]=fminf(s3[3],z3[2]); s3[1]=fminf(s3[2],z3[1]); s3[0]=fminf(s3[1],z3[0]);

    float x1 = __shfl_up_sync(FULL, a1[3], 1); if (lane == 0) x1 = INF;
    float x2 = __shfl_up_sync(FULL, a2[3], 1); if (lane == 0) x2 = INF;
    float y3 = __shfl_down_sync(FULL, s3[0], 1); if (lane == 31) y3 = INF;
    #pragma unroll
    for (int o = 1; o < 32; o <<= 1) {
        x1 = fminf(x1, __shfl_up_sync(FULL, x1, o));
        x2 = fminf(x2, __shfl_up_sync(FULL, x2, o));
        y3 = fminf(y3, __shfl_down_sync(FULL, y3, o));
    }
    if (lane == 31) { wtmp[w] = fminf(a1[3], x1); wtmp[4+w] = fminf(a2[3], x2); }
    if (lane == 0)  { wtmp[8+w] = fminf(s3[0], y3); }
    __syncthreads();   // lv0 + warp totals visible

    float o1 = INF, o2 = INF, o3 = INF;
    if (w > 0) { o1 = wtmp[0]; o2 = wtmp[4]; }
    if (w > 1) { o1 = fminf(o1, wtmp[1]); o2 = fminf(o2, wtmp[5]); }
    if (w > 2) { o1 = fminf(o1, wtmp[2]); o2 = fminf(o2, wtmp[6]); }
    if (w < 3) o3 = wtmp[11];
    if (w < 2) o3 = fminf(o3, wtmp[10]);
    if (w < 1) o3 = fminf(o3, wtmp[9]);
    float xf1 = fminf(x1, o1), xf2 = fminf(x2, o2), yf3 = fminf(y3, o3);

    float p1v[4], p2v[4], s3v[4];
    #pragma unroll
    for (int c = 0; c < 4; c++) {
        p1v[c] = fminf(a1[c], xf1);
        p2v[c] = fminf(a2[c], xf2);
        s3v[c] = fminf(s3[c], yf3);
    }
    *reinterpret_cast<float4*>(sPref1+q0) = make_float4(p1v[0],p1v[1],p1v[2],p1v[3]);
    *reinterpret_cast<float4*>(sPref2+q0) = make_float4(p2v[0],p2v[1],p2v[2],p2v[3]);
    *reinterpret_cast<float4*>(sSuf3+q0)  = make_float4(s3v[0],s3v[1],s3v[2],s3v[3]);

    // sparse levels 1..4
    #pragma unroll
    for (int lv = 1; lv <= 4; lv++) {
        int st = 1 << (lv-1);
        float q2[4], q3[4];
        #pragma unroll
        for (int c = 0; c < 4; c++) {
            int idx = q0 + c + st; if (idx > 511) idx = 511;
            q2[c] = sT2[lv-1][idx]; q3[c] = sT3[lv-1][idx];
        }
        #pragma unroll
        for (int c = 0; c < 4; c++) { z2[c] = fminf(z2[c], q2[c]); z3[c] = fminf(z3[c], q3[c]); }
        *reinterpret_cast<float4*>(&sT2[lv][q0]) = make_float4(z2[0],z2[1],z2[2],z2[3]);
        *reinterpret_cast<float4*>(&sT3[lv][q0]) = make_float4(z3[0],z3[1],z3[2],z3[3]);
        __syncthreads();
    }
}

// Query bnd (x) K_TT at 4 columns (TT = 1..16, compile-time).
template<int TT>
__device__ __forceinline__ float4 kq4(int q0, const float* sPref1, const float* sPref2,
    const float* sSuf3, const float (*sT2)[512], const float (*sT3)[512])
{
    constexpr int KK = (TT+1 >= 16) ? 4 : ((TT+1 >= 8) ? 3 : ((TT+1 >= 4) ? 2 : 1));
    constexpr int PK = 1 << KK;
    const float A = 0.955f, BA = 1.3693f - 0.955f;
    const float At = A * (float)TT, BAt = BA * (float)TT;
    float r[4];
    #pragma unroll
    for (int c = 0; c < 4; c++) {
        int j = q0 + c;
        float jf = (float)j;
        float v;
        int aL = j - TT;
        if (aL >= 0) {
            float w2 = fminf(sT2[KK][aL], sT2[KK][j + 1 - PK]);
            v = fminf(BA*jf + At + w2, A*jf + BAt + sPref1[aL]);
        } else {
            v = BA*jf + At + sPref2[j];
        }
        int eR = j + TT;
        float w3 = (eR <= 511) ? fminf(sT3[KK][j], sT3[KK][eR + 1 - PK]) : sSuf3[j];
        v = fminf(v, At - BA*jf + w3);
        r[c] = v;
    }
    return make_float4(r[0], r[1], r[2], r[3]);
}

// ---------------------------------------------------------------------------
// Stage 1: boundary (fused) + phase A pass 1; stores ALL 16 local rows.
__global__ void __launch_bounds__(128, 1) kA1(const int* __restrict__ tgt) {
    __shared__ float sm_lb[2][4], sm_rb[2][4];
    const float A = 0.955f, INF = 1.0e6f;
    int m = blockIdx.x, b = blockIdx.y;
    int t = threadIdx.x, lane = t & 31, w = t >> 5;
    int c0 = 4 * t, R0 = RB * m;
    const int* tb = tgt + (size_t)b * NPIX;

    unsigned sb[4] = {0, 0, 0, 0};
    int cD0[4] = {0,0,0,0}, cE0[4] = {1,1,1,1};
    int cD1[4] = {0,0,0,0}, cE1[4] = {1,1,1,1};
    int mc1[4] = {0,0,0,0};
    for (int rr = R0 - 1; rr <= R0 + RB; rr++) {
        int cD2[4], cE2[4], mc2[4];
        if ((unsigned)rr < HH) {
            const int* row = tb + rr * WW;
            int4 q = *reinterpret_cast<const int4*>(row + c0);
            int v1 = q.x > 0, v2 = q.y > 0, v3 = q.z > 0, v4 = q.w > 0;
            int hd0, he0, hd5, he5;
            if (c0 > 0)      { int mm = row[c0-1] > 0; hd0 = mm; he0 = mm; }
            else             { hd0 = 0; he0 = 1; }
            if (c0 + 4 < WW) { int mm = row[c0+4] > 0; hd5 = mm; he5 = mm; }
            else             { hd5 = 0; he5 = 1; }
            cD2[0] = hd0|v1|v2; cE2[0] = he0&v1&v2;
            cD2[1] = v1|v2|v3;  cE2[1] = v1&v2&v3;
            cD2[2] = v2|v3|v4;  cE2[2] = v2&v3&v4;
            cD2[3] = v3|v4|hd5; cE2[3] = v3&v4&he5;
            mc2[0] = v1; mc2[1] = v2; mc2[2] = v3; mc2[3] = v4;
        } else {
            #pragma unroll
            for (int c = 0; c < 4; c++) { cD2[c] = 0; cE2[c] = 1; mc2[c] = 0; }
        }
        if (rr > R0) {
            int u = rr - 1 - R0;
            unsigned pack = 0;
            #pragma unroll
            for (int c = 0; c < 4; c++) {
                int bd = (cD0[c]|cD1[c]|cD2[c]) & ((cE0[c]&cE1[c]&cE2[c]) ^ 1);
                pack |= (unsigned)(bd | (mc1[c] << 1)) << (8*c);
                sb[c] |= (unsigned)bd << u;
            }
            *reinterpret_cast<unsigned*>(g_bmask + (size_t)b*NPIX + (rr-1)*WW + c0) = pack;
        }
        #pragma unroll
        for (int c = 0; c < 4; c++) {
            cD0[c] = cD1[c]; cE0[c] = cE1[c];
            cD1[c] = cD2[c]; cE1[c] = cE2[c];
            mc1[c] = mc2[c];
        }
    }

    const float aj0 = A*(float)c0,     aj1 = A*(float)(c0+1);
    const float aj2 = A*(float)(c0+2), aj3 = A*(float)(c0+3);
    const float ajL = A*(float)(c0-1), ajR = A*(float)(c0+4);
    float p0 = INF, p1 = INF, p2 = INF, p3 = INF, hl = INF, hr = INF;
    for (int u = 0; u < RB; u++) {
        float v0 = ((sb[0] >> u) & 1u) ? 0.0f : INF;
        float v1 = ((sb[1] >> u) & 1u) ? 0.0f : INF;
        float v2 = ((sb[2] >> u) & 1u) ? 0.0f : INF;
        float v3 = ((sb[3] >> u) & 1u) ? 0.0f : INF;
        row_step(v0, v1, v2, v3, p0, p1, p2, p3, hl, hr,
                 aj0, aj1, aj2, aj3, ajL, ajR, lane, w, u & 1, sm_lb, sm_rb);
        *reinterpret_cast<float4*>(g_d + (size_t)b*NPIX + (R0+u)*WW + c0) =
            make_float4(p0, p1, p2, p3);
    }
    float4 val = make_float4(p0, p1, p2, p3);
    *reinterpret_cast<float4*>(g_lr1 + ((size_t)b*MB + m)*WW + c0) = val;
    *reinterpret_cast<float4*>(g_bn1 + ((size_t)b*MB + m)*WW + c0) = val;
}

// ---------------------------------------------------------------------------
// Chunked band conv: block (p, chunk, b) serves dests m = p+1+4*chunk+d, d=0..3.
// Per-column structures shared; per-d only the window selection differs.
template<int P>
__global__ void __launch_bounds__(128, 8) k_conv() {
    __shared__ float sp1[512], ss2[512], sp3[512];
    __shared__ float tT1[32], tT2[32], tT3[32];
    __shared__ float aT1[32], aT2p[32], aT3s[32];
    __shared__ float aW2[4][32], aW3[4][32];
    const float A = 0.955f, BA = 1.3693f - 0.955f, INF = 1.0e6f;
    int p = blockIdx.x, chunk = blockIdx.y, b = blockIdx.z;
    int m0 = p + 1 + 4*chunk;
    if (m0 >= MB) return;
    const float* LR = (P == 1) ? g_lr1 : g_lr2;
    float* BN = (P == 1) ? g_bn1 : g_bn2;
    int n0 = m0 - p;

    int tid = threadIdx.x, w = tid >> 5, sub = tid & 3;
    int q0 = 4*tid, sj = q0 >> 4, o = q0 & 15;

    const float* L = LR + ((size_t)b*MB + p)*WW;
    float4 lv = *reinterpret_cast<const float4*>(L + q0);
    float l[4] = {lv.x, lv.y, lv.z, lv.w};
    float z1[4], z2[4], z3[4];
    #pragma unroll
    for (int c = 0; c < 4; c++) {
        float j = (float)(q0 + c);
        z1[c] = l[c] - A * j;
        z2[c] = l[c] - BA * j;
        z3[c] = l[c] + BA * j;
    }
    float a1[4]; a1[0]=z1[0]; a1[1]=fminf(a1[0],z1[1]); a1[2]=fminf(a1[1],z1[2]); a1[3]=fminf(a1[2],z1[3]);
    float a2[4]; a2[0]=z2[0]; a2[1]=fminf(a2[0],z2[1]); a2[2]=fminf(a2[1],z2[2]); a2[3]=fminf(a2[2],z2[3]);
    float s2v[4]; s2v[3]=z2[3]; s2v[2]=fminf(s2v[3],z2[2]); s2v[1]=fminf(s2v[2],z2[1]); s2v[0]=fminf(s2v[1],z2[0]);
    float a3[4]; a3[0]=z3[0]; a3[1]=fminf(a3[0],z3[1]); a3[2]=fminf(a3[1],z3[2]); a3[3]=fminf(a3[2],z3[3]);
    float s3v[4]; s3v[3]=z3[3]; s3v[2]=fminf(s3v[3],z3[2]); s3v[1]=fminf(s3v[2],z3[1]); s3v[0]=fminf(s3v[1],z3[0]);

    float e1 = __shfl_up_sync(FULL, a1[3], 1, 4); if (sub == 0) e1 = INF;
    e1 = fminf(e1, __shfl_up_sync(FULL, e1, 1, 4));
    e1 = fminf(e1, __shfl_up_sync(FULL, e1, 2, 4));
    float e2 = __shfl_up_sync(FULL, a2[3], 1, 4); if (sub == 0) e2 = INF;
    e2 = fminf(e2, __shfl_up_sync(FULL, e2, 1, 4));
    e2 = fminf(e2, __shfl_up_sync(FULL, e2, 2, 4));
    float e3 = __shfl_up_sync(FULL, a3[3], 1, 4); if (sub == 0) e3 = INF;
    e3 = fminf(e3, __shfl_up_sync(FULL, e3, 1, 4));
    e3 = fminf(e3, __shfl_up_sync(FULL, e3, 2, 4));
    float f2 = __shfl_down_sync(FULL, s2v[0], 1, 4); if (sub == 3) f2 = INF;
    f2 = fminf(f2, __shfl_down_sync(FULL, f2, 1, 4));
    f2 = fminf(f2, __shfl_down_sync(FULL, f2, 2, 4));
    float f3 = __shfl_down_sync(FULL, s3v[0], 1, 4); if (sub == 3) f3 = INF;
    f3 = fminf(f3, __shfl_down_sync(FULL, f3, 1, 4));
    f3 = fminf(f3, __shfl_down_sync(FULL, f3, 2, 4));

    float sp1r[4], sp2r[4], ss2r[4], sp3r[4], ss3r[4];
    #pragma unroll
    for (int c = 0; c < 4; c++) {
        sp1r[c] = fminf(a1[c], e1);
        sp2r[c] = fminf(a2[c], e2);
        ss2r[c] = fminf(s2v[c], f2);
        sp3r[c] = fminf(a3[c], e3);
        ss3r[c] = fminf(s3v[c], f3);
    }
    *reinterpret_cast<float4*>(sp1 + q0) = make_float4(sp1r[0], sp1r[1], sp1r[2], sp1r[3]);
    *reinterpret_cast<float4*>(ss2 + q0) = make_float4(ss2r[0], ss2r[1], ss2r[2], ss2r[3]);
    *reinterpret_cast<float4*>(sp3 + q0) = make_float4(sp3r[0], sp3r[1], sp3r[2], sp3r[3]);
    if (sub == 3) { tT1[sj] = sp1r[3]; tT2[sj] = sp2r[3]; tT3[sj] = sp3r[3]; }
    __syncthreads();

    if (w == 0) {
        float v = tT1[tid];
        #pragma unroll
        for (int oo = 1; oo < 32; oo <<= 1) v = fminf(v, __shfl_up_sync(FULL, v, oo));
        aT1[tid] = v;
    } else if (w == 1) {
        int s = tid & 31;
        float T = tT2[s];
        float v = T;
        #pragma unroll
        for (int oo = 1; oo < 32; oo <<= 1) v = fminf(v, __shfl_up_sync(FULL, v, oo));
        aT2p[s] = v;
        float M1 = T;
        float M2  = fminf(M1,  __shfl_up_sync(FULL, M1, 1));
        float M4  = fminf(M2,  __shfl_up_sync(FULL, M2, 2));
        float M8  = fminf(M4,  __shfl_up_sync(FULL, M4, 4));
        float M16 = fminf(M8,  __shfl_up_sync(FULL, M8, 8));
        #pragma unroll
        for (int d = 0; d < 4; d++) {
            int Lw = n0 + d - 1;
            if (m0 + d < MB && Lw >= 1) {
                float Mp; int pw;
                if      (Lw >= 16) { Mp = M16; pw = 16; }
                else if (Lw >= 8)  { Mp = M8;  pw = 8; }
                else if (Lw >= 4)  { Mp = M4;  pw = 4; }
                else if (Lw >= 2)  { Mp = M2;  pw = 2; }
                else               { Mp = M1;  pw = 1; }
                aW2[d][s] = fminf(Mp, __shfl_up_sync(FULL, Mp, Lw - pw));
            }
        }
    } else if (w == 2) {
        int s = tid & 31;
        float T = tT3[s];
        float v = T;
        #pragma unroll
        for (int oo = 1; oo < 32; oo <<= 1) v = fminf(v, __shfl_down_sync(FULL, v, oo));
        aT3s[s] = v;
        float N1 = T;
        float N2  = fminf(N1,  __shfl_down_sync(FULL, N1, 1));
        float N4  = fminf(N2,  __shfl_down_sync(FULL, N2, 2));
        float N8  = fminf(N4,  __shfl_down_sync(FULL, N4, 4));
        float N16 = fminf(N8,  __shfl_down_sync(FULL, N8, 8));
        #pragma unroll
        for (int d = 0; d < 4; d++) {
            int Lw = n0 + d - 1;
            if (m0 + d < MB && Lw >= 1) {
                float Np; int pw;
                if      (Lw >= 16) { Np = N16; pw = 16; }
                else if (Lw >= 8)  { Np = N8;  pw = 8; }
                else if (Lw >= 4)  { Np = N4;  pw = 4; }
                else if (Lw >= 2)  { Np = N2;  pw = 2; }
                else               { Np = N1;  pw = 1; }
                aW3[d][s] = fminf(Np, __shfl_down_sync(FULL, Np, Lw - pw));
            }
        }
    }
    __syncthreads();

    #pragma unroll
    for (int d = 0; d < 4; d++) {
        int m = m0 + d;
        if (m >= MB) break;
        int n = n0 + d;
        int t = n * RB;
        int Lw = n - 1;
        float At = A * (float)t, BAt = BA * (float)t;
        int* dst = reinterpret_cast<int*>(BN + ((size_t)b*MB + m)*WW + q0);
        int sa = sj - n, sb_ = sj + n;
        float w2mid = (sa >= 0 && Lw >= 1) ? aW2[d][sj - 1] : INF;
        float gp2t  = (sa < 0 && sj > 0)  ? aT2p[sj - 1] : INF;
        float w3mid = (sb_ <= 31 && Lw >= 1) ? aW3[d][sj + 1] : INF;
        float gs3t  = (sb_ > 31 && sj < 31) ? aT3s[sj + 1] : INF;

        #pragma unroll
        for (int c = 0; c < 4; c++) {
            float jf = (float)(q0 + c);
            float w2;
            if (sa < 0) w2 = fminf(sp2r[c], gp2t);
            else        w2 = fminf(fminf(ss2[sa*16 + o + c], sp2r[c]), w2mid);
            float best = BA * jf + At + w2;
            float w3;
            if (sb_ > 31) w3 = fminf(ss3r[c], gs3t);
            else          w3 = fminf(fminf(ss3r[c], sp3[sb_*16 + o + c]), w3mid);
            best = fminf(best, At - BA * jf + w3);
            int jt = q0 + c - t;
            if (jt >= 0) {
                int seg = jt >> 4;
                float pm = sp1[jt];
                if (seg > 0) pm = fminf(pm, aT1[seg - 1]);
                best = fminf(best, A * jf + BAt + pm);
            }
            atomicMin(dst + c, __float_as_int(best));
        }
    }
}

// ---------------------------------------------------------------------------
// Stage 3: parallel C1 (conv-min, overwrites g_d) + serial A2 (stores g_d2).
__global__ void __launch_bounds__(128, 1) kC1A2() {
    __shared__ float sm_lb[2][4], sm_rb[2][4];
    __shared__ float sPref1[512], sPref2[512], sSuf3[512];
    __shared__ float sT2[5][512], sT3[5][512];
    __shared__ float wtmp[12];
    const float A = 0.955f, INF = 1.0e6f;
    int m = blockIdx.x, b = blockIdx.y;
    int t = threadIdx.x, lane = t & 31, w = t >> 5;
    int q0 = 4 * t;

    const float* br = (m > 0) ? (g_bn1 + ((size_t)b*MB + (m-1))*WW) : nullptr;
    build_ktab(br, q0, lane, w, sPref1, sPref2, sSuf3, sT2, sT3, wtmp);

    float* gd = g_d + (size_t)b*NPIX + (RB*m)*WW;
    #define C1ROW(U) { \
        float4 dv = *reinterpret_cast<const float4*>(gd + (U)*WW + q0); \
        float4 qv = kq4<(U)+1>(q0, sPref1, sPref2, sSuf3, \
            (const float(*)[512])sT2, (const float(*)[512])sT3); \
        *reinterpret_cast<float4*>(gd + (U)*WW + q0) = make_float4( \
            fminf(dv.x,qv.x), fminf(dv.y,qv.y), fminf(dv.z,qv.z), fminf(dv.w,qv.w)); }
    C1ROW(0)  C1ROW(1)  C1ROW(2)  C1ROW(3)
    C1ROW(4)  C1ROW(5)  C1ROW(6)  C1ROW(7)
    C1ROW(8)  C1ROW(9)  C1ROW(10) C1ROW(11)
    C1ROW(12) C1ROW(13) C1ROW(14) C1ROW(15)
    #undef C1ROW
    __syncthreads();   // C1 global writes visible block-wide

    // A2 for pass-2 band (MB-1-m): serial local evolution over reversed rows.
    const float aj0 = A*(float)q0,     aj1 = A*(float)(q0+1);
    const float aj2 = A*(float)(q0+2), aj3 = A*(float)(q0+3);
    const float ajL = A*(float)(q0-1), ajR = A*(float)(q0+4);
    float p0 = INF, p1 = INF, p2 = INF, p3 = INF, hl = INF, hr = INF;
    int band2 = MB - 1 - m;
    float* gd2 = g_d2 + ((size_t)b*MB + band2)*(RB*WW);

    float4 nv  = *reinterpret_cast<const float4*>(gd + (RB-1)*WW + (WW-4-q0));
    float4 nv2 = *reinterpret_cast<const float4*>(gd + (RB-2)*WW + (WW-4-q0));
    for (int u2 = 0; u2 < RB; u2++) {
        float4 cu = nv; nv = nv2;
        if (u2 + 2 < RB)
            nv2 = *reinterpret_cast<const float4*>(gd + (RB-3-u2)*WW + (WW-4-q0));
        row_step(cu.w, cu.z, cu.y, cu.x, p0, p1, p2, p3, hl, hr,
                 aj0, aj1, aj2, aj3, ajL, ajR, lane, w, u2 & 1, sm_lb, sm_rb);
        *reinterpret_cast<float4*>(gd2 + u2*WW + q0) = make_float4(p0, p1, p2, p3);
    }
    float4 val = make_float4(p0, p1, p2, p3);
    *reinterpret_cast<float4*>(g_lr2 + ((size_t)b*MB + band2)*WW + q0) = val;
    *reinterpret_cast<float4*>(g_bn2 + ((size_t)b*MB + band2)*WW + q0) = val;
}

// ---------------------------------------------------------------------------
__device__ __forceinline__ void loss_px(float x, float tv, float draw,
    float& fs, float& bA, float& bD, float& iS, float& pS, float& tS)
{
    float ax = fabsf(x);
    float ea = __expf(-ax);
    float den = 1.0f + ea;
    float rr = 1.0f / den;
    float pp = (x >= 0.f) ? rr : ea * rr;
    float ls = fminf(x, 0.f) - __logf(den);
    float bce = (1.f - tv) * x - ls;
    float pt  = (tv == 1.f) ? pp : 1.f - pp;
    float at  = (tv == 1.f) ? 0.25f : 0.75f;
    float omp = 1.f - pt;
    fs += at * omp * omp * bce;
    float base = tv * (1.f - pp) + (1.f - tv) * pp;
    bA += base;
    bD += base * draw;
    iS += pp * tv; pS += pp; tS += tv;
}

// Stage 5: parallel C2 (conv-min) + inline loss; no serial chain.
__global__ void __launch_bounds__(128, 1) kC2L(const float* __restrict__ pred) {
    __shared__ float sPref1[512], sPref2[512], sSuf3[512];
    __shared__ float sT2[5][512], sT3[5][512];
    __shared__ float wtmp[12];
    __shared__ float red[4][6];
    int m = blockIdx.x, b = blockIdx.y;
    int t = threadIdx.x, lane = t & 31, w = t >> 5;
    int q0 = 4 * t;
    size_t base = (size_t)b * NPIX;

    const float* br = (m > 0) ? (g_bn2 + ((size_t)b*MB + (m-1))*WW) : nullptr;
    build_ktab(br, q0, lane, w, sPref1, sPref2, sSuf3, sT2, sT3, wtmp);

    const float* gd2 = g_d2 + ((size_t)b*MB + m)*(RB*WW);
    float fs = 0.f, bA = 0.f, bD = 0.f, iS = 0.f, pS = 0.f, tS = 0.f;
    float mx = -1.0f;
    #define C2ROW(U) { \
        float4 dv = *reinterpret_cast<const float4*>(gd2 + (U)*WW + q0); \
        float4 qv = kq4<(U)+1>(q0, sPref1, sPref2, sSuf3, \
            (const float(*)[512])sT2, (const float(*)[512])sT3); \
        float d0 = fminf(dv.x, qv.x), d1 = fminf(dv.y, qv.y); \
        float d2 = fminf(dv.z, qv.z), d3 = fminf(dv.w, qv.w); \
        mx = fmaxf(fmaxf(mx, fmaxf(d0, d1)), fmaxf(d2, d3)); \
        int pr = HH - 1 - (RB*m + (U)); \
        float4 xv = *reinterpret_cast<const float4*>(pred + base + pr*WW + (WW-4-q0)); \
        unsigned um = *reinterpret_cast<const unsigned*>(g_bmask + base + pr*WW + (WW-4-q0)); \
        loss_px(xv.x, (float)((um >> 1)  & 1u), d3, fs, bA, bD, iS, pS, tS); \
        loss_px(xv.y, (float)((um >> 9)  & 1u), d2, fs, bA, bD, iS, pS, tS); \
        loss_px(xv.z, (float)((um >> 17) & 1u), d1, fs, bA, bD, iS, pS, tS); \
        loss_px(xv.w, (float)((um >> 25) & 1u), d0, fs, bA, bD, iS, pS, tS); }
    C2ROW(0)  C2ROW(1)  C2ROW(2)  C2ROW(3)
    C2ROW(4)  C2ROW(5)  C2ROW(6)  C2ROW(7)
    C2ROW(8)  C2ROW(9)  C2ROW(10) C2ROW(11)
    C2ROW(12) C2ROW(13) C2ROW(14) C2ROW(15)
    #undef C2ROW

    #pragma unroll
    for (int o = 16; o > 0; o >>= 1) {
        fs += __shfl_xor_sync(FULL, fs, o);
        bA += __shfl_xor_sync(FULL, bA, o);
        bD += __shfl_xor_sync(FULL, bD, o);
        iS += __shfl_xor_sync(FULL, iS, o);
        pS += __shfl_xor_sync(FULL, pS, o);
        tS += __shfl_xor_sync(FULL, tS, o);
        mx  = fmaxf(mx, __shfl_xor_sync(FULL, mx, o));
    }
    if (lane == 0) {
        red[w][0] = fs; red[w][1] = bA; red[w][2] = bD;
        red[w][3] = iS; red[w][4] = pS; red[w][5] = tS;
        atomicMax(&g_mxi[b], __float_as_int(mx));
    }
    __syncthreads();
    if (t == 0) {
        float a0=0,a1=0,a2=0,a3=0,a4=0,a5=0;
        #pragma unroll
        for (int ww = 0; ww < 4; ww++) {
            a0+=red[ww][0]; a1+=red[ww][1]; a2+=red[ww][2];
            a3+=red[ww][3]; a4+=red[ww][4]; a5+=red[ww][5];
        }
        atomicAdd(&g_acc[0], (double)a0);
        atomicAdd(&g_acc[1], (double)a1);
        atomicAdd(&g_acc[2 + b],        (double)a2);
        atomicAdd(&g_acc[2 + NB + b],   (double)a3);
        atomicAdd(&g_acc[2 + 2*NB + b], (double)a4);
        atomicAdd(&g_acc[2 + 3*NB + b], (double)a5);
    }
}

// ---------------------------------------------------------------------------
__global__ void k_final(const float* __restrict__ lv, float* __restrict__ out) {
    double N = (double)NB * (double)NPIX;
    double focal = g_acc[0] / N;
    double bndsum = g_acc[1];
    double ds = 0.0, us = 0.0;
    for (int b = 0; b < NB; b++) {
        double mx = (double)__int_as_float(g_mxi[b]);
        double dd = g_acc[2 + b];
        bndsum += (mx > 0.0) ? dd / mx : dd;
        double inter = g_acc[2 + NB + b];
        double tot   = g_acc[2 + 2*NB + b] + g_acc[2 + 3*NB + b];
        ds += (2.0*inter + 1e-6) / (tot + 1e-6);
        us += (inter + 1e-6) / (tot - inter + 1e-6);
    }
    double bnd  = bndsum / N;
    double dice = 1.0 - ds / NB;
    double iou  = 1.0 - us / NB;
    double l0 = lv[0], l1 = lv[1], l2 = lv[2], l3 = lv[3];
    double total = exp(-l0)*focal + l0 + exp(-l1)*dice + l1
                 + exp(-l2)*bnd + l2 + exp(-l3)*iou + l3;
    out[0] = (float)total;
    out[1] = (float)focal;
    out[2] = (float)dice;
    out[3] = (float)bnd;
    out[4] = (float)iou;
    for (int i = 0; i < 2 + 4*NB; i++) g_acc[i] = 0.0;
    for (int i = 0; i < NB; i++) g_mxi[i] = 0;
}

// ---------------------------------------------------------------------------
extern "C" void kernel_launch(void* const* d_in, const int* in_sizes, int n_in,
                              void* d_out, int out_size) {
    const float* pred = (const float*)d_in[0];
    const int*   tgt  = (const int*)d_in[1];
    const float* lv   = (const float*)d_in[2];
    float* out = (float*)d_out;

    kA1<<<dim3(MB, NB), 128>>>(tgt);
    k_conv<1><<<dim3(MB-1, 8, NB), 128>>>();
    kC1A2<<<dim3(MB, NB), 128>>>();
    k_conv<2><<<dim3(MB-1, 8, NB), 128>>>();
    kC2L<<<dim3(MB, NB), 128>>>(pred);
    k_final<<<1, 1>>>(lv, out);
}

// round 12
// speedup vs baseline: 1.1827x; 1.1827x over previous
#include <cuda_runtime.h>
#include <cstdint>

#define HH 512
#define WW 512
#define NB 16
#define NPIX (HH*WW)
#define RB 16
#define MB (HH/RB)        // 32
#define FULL 0xffffffffu

static __device__ float g_d[NB*NPIX];             // pass-1 final dist
static __device__ unsigned char g_bmask[NB*NPIX]; // bit0 boundary, bit1 target
static __device__ int g_mxi[NB];
static __device__ float g_lr1[NB*MB*WW], g_bn1[NB*MB*WW];
static __device__ float g_lr2[NB*MB*WW], g_bn2[NB*MB*WW];
static __device__ double g_acc[2 + 4*NB];

// ---------------------------------------------------------------------------
// One chamfer row-step: 128 threads / 4 warps, 4 cols/thread, 8 shfls, 1 bar.
__device__ __forceinline__ void row_step(
    float v0, float v1, float v2, float v3,
    float& p0, float& p1, float& p2, float& p3, float& hl, float& hr,
    float aj0, float aj1, float aj2, float aj3, float ajL, float ajR,
    int lane, int w, int par,
    float (*sm_lb)[4], float (*sm_rb)[4])
{
    const float A = 0.955f, Bd = 1.3693f, INF = 1.0e6f;
    float s0 = fminf(fminf(v0, p0 + A), fminf(hl + Bd, p1 + Bd)) - aj0;
    float s1 = fminf(fminf(v1, p1 + A), fminf(p0 + Bd, p2 + Bd)) - aj1;
    float s2 = fminf(fminf(v2, p2 + A), fminf(p1 + Bd, p3 + Bd)) - aj2;
    float s3 = fminf(fminf(v3, p3 + A), fminf(p2 + Bd, hr + Bd)) - aj3;

    float run1 = fminf(s0, s1);
    float run2 = fminf(run1, s2);
    float run3 = fminf(run2, s3);

    float x = __shfl_up_sync(FULL, run3, 1);
    if (lane == 0) x = INF;
    #pragma unroll
    for (int o = 1; o < 32; o <<= 1)
        x = fminf(x, __shfl_up_sync(FULL, x, o));

    if (lane == 31) sm_lb[par][w] = fminf(run3, x);   // warp inclusive total
    if (lane == 0)  sm_rb[par][w] = s0;
    __syncthreads();

    float t0s = sm_lb[par][0], t1s = sm_lb[par][1], t2s = sm_lb[par][2];
    float offw = INF;
    if (w > 0) offw = t0s;
    if (w > 1) offw = fminf(offw, t1s);
    if (w > 2) offw = fminf(offw, t2s);
    float xf = fminf(x, offw);

    float c0 = aj0 + fminf(s0,  xf);
    float c1 = aj1 + fminf(run1, xf);
    float c2 = aj2 + fminf(run2, xf);
    float c3 = aj3 + fminf(run3, xf);

    float nhl = __shfl_up_sync(FULL, c3, 1);
    float nhr = __shfl_down_sync(FULL, c0, 1);
    if (lane == 0) {
        if (w == 0) nhl = INF;
        else {
            float offm = INF;
            if (w - 1 > 0) offm = t0s;
            if (w - 1 > 1) offm = fminf(offm, t1s);
            nhl = ajL + fminf(sm_lb[par][w-1], offm);
        }
    }
    if (lane == 31) {
        if (w == 3) nhr = INF;
        else {
            float own = fminf(run3, x);
            nhr = ajR + fminf(sm_rb[par][w+1], fminf(own, offw));
        }
    }
    hl = nhl; hr = nhr;
    p0 = c0; p1 = c1; p2 = c2; p3 = c3;
}

__device__ __forceinline__ void load_init(const float* br, int q0, int lane,
                                          float& p0, float& p1, float& p2, float& p3,
                                          float& hl, float& hr)
{
    const float INF = 1.0e6f;
    float4 pv = *reinterpret_cast<const float4*>(br + q0);
    p0 = pv.x; p1 = pv.y; p2 = pv.z; p3 = pv.w;
    float sl = __shfl_up_sync(FULL, p3, 1);
    float sr = __shfl_down_sync(FULL, p0, 1);
    hl = (q0 == 0) ? INF : ((lane == 0) ? br[q0-1] : sl);
    hr = (q0 + 4 >= WW) ? INF : ((lane == 31) ? br[q0+4] : sr);
}

// ---------------------------------------------------------------------------
// Stage 1: boundary (fused) + phase A pass 1.
__global__ void __launch_bounds__(128, 1) kA1(const int* __restrict__ tgt) {
    __shared__ float sm_lb[2][4], sm_rb[2][4];
    const float A = 0.955f, INF = 1.0e6f;
    int m = blockIdx.x, b = blockIdx.y;
    int t = threadIdx.x, lane = t & 31, w = t >> 5;
    int c0 = 4 * t, R0 = RB * m;
    const int* tb = tgt + (size_t)b * NPIX;

    unsigned sb[4] = {0, 0, 0, 0};
    int cD0[4] = {0,0,0,0}, cE0[4] = {1,1,1,1};
    int cD1[4] = {0,0,0,0}, cE1[4] = {1,1,1,1};
    int mc1[4] = {0,0,0,0};
    for (int rr = R0 - 1; rr <= R0 + RB; rr++) {
        int cD2[4], cE2[4], mc2[4];
        if ((unsigned)rr < HH) {
            const int* row = tb + rr * WW;
            int4 q = *reinterpret_cast<const int4*>(row + c0);
            int v1 = q.x > 0, v2 = q.y > 0, v3 = q.z > 0, v4 = q.w > 0;
            int hd0, he0, hd5, he5;
            if (c0 > 0)      { int mm = row[c0-1] > 0; hd0 = mm; he0 = mm; }
            else             { hd0 = 0; he0 = 1; }
            if (c0 + 4 < WW) { int mm = row[c0+4] > 0; hd5 = mm; he5 = mm; }
            else             { hd5 = 0; he5 = 1; }
            cD2[0] = hd0|v1|v2; cE2[0] = he0&v1&v2;
            cD2[1] = v1|v2|v3;  cE2[1] = v1&v2&v3;
            cD2[2] = v2|v3|v4;  cE2[2] = v2&v3&v4;
            cD2[3] = v3|v4|hd5; cE2[3] = v3&v4&he5;
            mc2[0] = v1; mc2[1] = v2; mc2[2] = v3; mc2[3] = v4;
        } else {
            #pragma unroll
            for (int c = 0; c < 4; c++) { cD2[c] = 0; cE2[c] = 1; mc2[c] = 0; }
        }
        if (rr > R0) {
            int u = rr - 1 - R0;
            unsigned pack = 0;
            #pragma unroll
            for (int c = 0; c < 4; c++) {
                int bd = (cD0[c]|cD1[c]|cD2[c]) & ((cE0[c]&cE1[c]&cE2[c]) ^ 1);
                pack |= (unsigned)(bd | (mc1[c] << 1)) << (8*c);
                sb[c] |= (unsigned)bd << u;
            }
            *reinterpret_cast<unsigned*>(g_bmask + (size_t)b*NPIX + (rr-1)*WW + c0) = pack;
        }
        #pragma unroll
        for (int c = 0; c < 4; c++) {
            cD0[c] = cD1[c]; cE0[c] = cE1[c];
            cD1[c] = cD2[c]; cE1[c] = cE2[c];
            mc1[c] = mc2[c];
        }
    }

    const float aj0 = A*(float)c0,     aj1 = A*(float)(c0+1);
    const float aj2 = A*(float)(c0+2), aj3 = A*(float)(c0+3);
    const float ajL = A*(float)(c0-1), ajR = A*(float)(c0+4);
    float p0 = INF, p1 = INF, p2 = INF, p3 = INF, hl = INF, hr = INF;
    for (int u = 0; u < RB; u++) {
        float v0 = ((sb[0] >> u) & 1u) ? 0.0f : INF;
        float v1 = ((sb[1] >> u) & 1u) ? 0.0f : INF;
        float v2 = ((sb[2] >> u) & 1u) ? 0.0f : INF;
        float v3 = ((sb[3] >> u) & 1u) ? 0.0f : INF;
        row_step(v0, v1, v2, v3, p0, p1, p2, p3, hl, hr,
                 aj0, aj1, aj2, aj3, ajL, ajR, lane, w, u & 1, sm_lb, sm_rb);
    }
    float4 val = make_float4(p0, p1, p2, p3);
    *reinterpret_cast<float4*>(g_lr1 + ((size_t)b*MB + m)*WW + c0) = val;
    *reinterpret_cast<float4*>(g_bn1 + ((size_t)b*MB + m)*WW + c0) = val;
}

// ---------------------------------------------------------------------------
// Chunked band conv: block (p, chunk, b) serves dests m = p+1+4*chunk+d, d=0..3.
// Per-column structures of L[p] are built once and shared across the 4 dests.
template<int P>
__global__ void __launch_bounds__(128, 8) k_conv() {
    __shared__ float sp1[512], ss2[512], sp3[512];
    __shared__ float tT1[32], tT2[32], tT3[32];
    __shared__ float aT1[32], aT2p[32], aT3s[32];
    __shared__ float aW2[4][32], aW3[4][32];
    const float A = 0.955f, BA = 1.3693f - 0.955f, INF = 1.0e6f;
    int p = blockIdx.x, chunk = blockIdx.y, b = blockIdx.z;
    int m0 = p + 1 + 4*chunk;
    if (m0 >= MB) return;
    const float* LR = (P == 1) ? g_lr1 : g_lr2;
    float* BN = (P == 1) ? g_bn1 : g_bn2;
    int n0 = m0 - p;

    int tid = threadIdx.x, w = tid >> 5, sub = tid & 3;
    int q0 = 4*tid, sj = q0 >> 4, o = q0 & 15;

    const float* L = LR + ((size_t)b*MB + p)*WW;
    float4 lv = *reinterpret_cast<const float4*>(L + q0);
    float l[4] = {lv.x, lv.y, lv.z, lv.w};
    float z1[4], z2[4], z3[4];
    #pragma unroll
    for (int c = 0; c < 4; c++) {
        float j = (float)(q0 + c);
        z1[c] = l[c] - A * j;
        z2[c] = l[c] - BA * j;
        z3[c] = l[c] + BA * j;
    }
    float a1[4]; a1[0]=z1[0]; a1[1]=fminf(a1[0],z1[1]); a1[2]=fminf(a1[1],z1[2]); a1[3]=fminf(a1[2],z1[3]);
    float a2[4]; a2[0]=z2[0]; a2[1]=fminf(a2[0],z2[1]); a2[2]=fminf(a2[1],z2[2]); a2[3]=fminf(a2[2],z2[3]);
    float s2v[4]; s2v[3]=z2[3]; s2v[2]=fminf(s2v[3],z2[2]); s2v[1]=fminf(s2v[2],z2[1]); s2v[0]=fminf(s2v[1],z2[0]);
    float a3[4]; a3[0]=z3[0]; a3[1]=fminf(a3[0],z3[1]); a3[2]=fminf(a3[1],z3[2]); a3[3]=fminf(a3[2],z3[3]);
    float s3v[4]; s3v[3]=z3[3]; s3v[2]=fminf(s3v[3],z3[2]); s3v[1]=fminf(s3v[2],z3[1]); s3v[0]=fminf(s3v[1],z3[0]);

    float e1 = __shfl_up_sync(FULL, a1[3], 1, 4); if (sub == 0) e1 = INF;
    e1 = fminf(e1, __shfl_up_sync(FULL, e1, 1, 4));
    e1 = fminf(e1, __shfl_up_sync(FULL, e1, 2, 4));
    float e2 = __shfl_up_sync(FULL, a2[3], 1, 4); if (sub == 0) e2 = INF;
    e2 = fminf(e2, __shfl_up_sync(FULL, e2, 1, 4));
    e2 = fminf(e2, __shfl_up_sync(FULL, e2, 2, 4));
    float e3 = __shfl_up_sync(FULL, a3[3], 1, 4); if (sub == 0) e3 = INF;
    e3 = fminf(e3, __shfl_up_sync(FULL, e3, 1, 4));
    e3 = fminf(e3, __shfl_up_sync(FULL, e3, 2, 4));
    float f2 = __shfl_down_sync(FULL, s2v[0], 1, 4); if (sub == 3) f2 = INF;
    f2 = fminf(f2, __shfl_down_sync(FULL, f2, 1, 4));
    f2 = fminf(f2, __shfl_down_sync(FULL, f2, 2, 4));
    float f3 = __shfl_down_sync(FULL, s3v[0], 1, 4); if (sub == 3) f3 = INF;
    f3 = fminf(f3, __shfl_down_sync(FULL, f3, 1, 4));
    f3 = fminf(f3, __shfl_down_sync(FULL, f3, 2, 4));

    float sp1r[4], sp2r[4], ss2r[4], sp3r[4], ss3r[4];
    #pragma unroll
    for (int c = 0; c < 4; c++) {
        sp1r[c] = fminf(a1[c], e1);
        sp2r[c] = fminf(a2[c], e2);
        ss2r[c] = fminf(s2v[c], f2);
        sp3r[c] = fminf(a3[c], e3);
        ss3r[c] = fminf(s3v[c], f3);
    }
    *reinterpret_cast<float4*>(sp1 + q0) = make_float4(sp1r[0], sp1r[1], sp1r[2], sp1r[3]);
    *reinterpret_cast<float4*>(ss2 + q0) = make_float4(ss2r[0], ss2r[1], ss2r[2], ss2r[3]);
    *reinterpret_cast<float4*>(sp3 + q0) = make_float4(sp3r[0], sp3r[1], sp3r[2], sp3r[3]);
    if (sub == 3) { tT1[sj] = sp1r[3]; tT2[sj] = sp2r[3]; tT3[sj] = sp3r[3]; }
    __syncthreads();

    if (w == 0) {
        float v = tT1[tid];
        #pragma unroll
        for (int oo = 1; oo < 32; oo <<= 1) v = fminf(v, __shfl_up_sync(FULL, v, oo));
        aT1[tid] = v;
    } else if (w == 1) {
        int s = tid & 31;
        float T = tT2[s];
        float v = T;
        #pragma unroll
        for (int oo = 1; oo < 32; oo <<= 1) v = fminf(v, __shfl_up_sync(FULL, v, oo));
        aT2p[s] = v;
        float M1 = T;
        float M2  = fminf(M1,  __shfl_up_sync(FULL, M1, 1));
        float M4  = fminf(M2,  __shfl_up_sync(FULL, M2, 2));
        float M8  = fminf(M4,  __shfl_up_sync(FULL, M4, 4));
        float M16 = fminf(M8,  __shfl_up_sync(FULL, M8, 8));
        #pragma unroll
        for (int d = 0; d < 4; d++) {
            int Lw = n0 + d - 1;
            if (m0 + d < MB && Lw >= 1) {
                float Mp; int pw;
                if      (Lw >= 16) { Mp = M16; pw = 16; }
                else if (Lw >= 8)  { Mp = M8;  pw = 8; }
                else if (Lw >= 4)  { Mp = M4;  pw = 4; }
                else if (Lw >= 2)  { Mp = M2;  pw = 2; }
                else               { Mp = M1;  pw = 1; }
                aW2[d][s] = fminf(Mp, __shfl_up_sync(FULL, Mp, Lw - pw));
            }
        }
    } else if (w == 2) {
        int s = tid & 31;
        float T = tT3[s];
        float v = T;
        #pragma unroll
        for (int oo = 1; oo < 32; oo <<= 1) v = fminf(v, __shfl_down_sync(FULL, v, oo));
        aT3s[s] = v;
        float N1 = T;
        float N2  = fminf(N1,  __shfl_down_sync(FULL, N1, 1));
        float N4  = fminf(N2,  __shfl_down_sync(FULL, N2, 2));
        float N8  = fminf(N4,  __shfl_down_sync(FULL, N4, 4));
        float N16 = fminf(N8,  __shfl_down_sync(FULL, N8, 8));
        #pragma unroll
        for (int d = 0; d < 4; d++) {
            int Lw = n0 + d - 1;
            if (m0 + d < MB && Lw >= 1) {
                float Np; int pw;
                if      (Lw >= 16) { Np = N16; pw = 16; }
                else if (Lw >= 8)  { Np = N8;  pw = 8; }
                else if (Lw >= 4)  { Np = N4;  pw = 4; }
                else if (Lw >= 2)  { Np = N2;  pw = 2; }
                else               { Np = N1;  pw = 1; }
                aW3[d][s] = fminf(Np, __shfl_down_sync(FULL, Np, Lw - pw));
            }
        }
    }
    __syncthreads();

    #pragma unroll
    for (int d = 0; d < 4; d++) {
        int m = m0 + d;
        if (m >= MB) break;
        int n = n0 + d;
        int t = n * RB;
        int Lw = n - 1;
        float At = A * (float)t, BAt = BA * (float)t;
        int* dst = reinterpret_cast<int*>(BN + ((size_t)b*MB + m)*WW + q0);
        int sa = sj - n, sb_ = sj + n;
        float w2mid = (sa >= 0 && Lw >= 1) ? aW2[d][sj - 1] : INF;
        float gp2t  = (sa < 0 && sj > 0)  ? aT2p[sj - 1] : INF;
        float w3mid = (sb_ <= 31 && Lw >= 1) ? aW3[d][sj + 1] : INF;
        float gs3t  = (sb_ > 31 && sj < 31) ? aT3s[sj + 1] : INF;

        #pragma unroll
        for (int c = 0; c < 4; c++) {
            float jf = (float)(q0 + c);
            float w2;
            if (sa < 0) w2 = fminf(sp2r[c], gp2t);
            else        w2 = fminf(fminf(ss2[sa*16 + o + c], sp2r[c]), w2mid);
            float best = BA * jf + At + w2;
            float w3;
            if (sb_ > 31) w3 = fminf(ss3r[c], gs3t);
            else          w3 = fminf(fminf(ss3r[c], sp3[sb_*16 + o + c]), w3mid);
            best = fminf(best, At - BA * jf + w3);
            int jt = q0 + c - t;
            if (jt >= 0) {
                int seg = jt >> 4;
                float pm = sp1[jt];
                if (seg > 0) pm = fminf(pm, aT1[seg - 1]);
                best = fminf(best, A * jf + BAt + pm);
            }
            atomicMin(dst + c, __float_as_int(best));
        }
    }
}

// ---------------------------------------------------------------------------
// Stage 3: phase C pass 1 (store g_d + smem) fused with phase A pass 2.
__global__ void __launch_bounds__(128, 1) kC1A2() {
    __shared__ float sm_lb[2][4], sm_rb[2][4];
    __shared__ float sbuf[RB][WW];
    const float A = 0.955f, INF = 1.0e6f;
    int m = blockIdx.x, b = blockIdx.y;
    int t = threadIdx.x, lane = t & 31, w = t >> 5;
    int q0 = 4 * t;
    const float aj0 = A*(float)q0,     aj1 = A*(float)(q0+1);
    const float aj2 = A*(float)(q0+2), aj3 = A*(float)(q0+3);
    const float ajL = A*(float)(q0-1), ajR = A*(float)(q0+4);

    float p0 = INF, p1 = INF, p2 = INF, p3 = INF, hl = INF, hr = INF;
    if (m > 0)
        load_init(g_bn1 + ((size_t)b*MB + (m-1))*WW, q0, lane, p0, p1, p2, p3, hl, hr);

    unsigned nv  = *reinterpret_cast<const unsigned*>(g_bmask + (size_t)b*NPIX + (RB*m)*WW + q0);
    unsigned nv2 = *reinterpret_cast<const unsigned*>(g_bmask + (size_t)b*NPIX + (RB*m+1)*WW + q0);
    for (int u = 0; u < RB; u++) {
        unsigned cu = nv; nv = nv2;
        if (u + 2 < RB)
            nv2 = *reinterpret_cast<const unsigned*>(g_bmask + (size_t)b*NPIX + (RB*m+u+2)*WW + q0);
        float v0 = (cu & 1u)         ? 0.0f : INF;
        float v1 = ((cu >> 8) & 1u)  ? 0.0f : INF;
        float v2 = ((cu >> 16) & 1u) ? 0.0f : INF;
        float v3 = ((cu >> 24) & 1u) ? 0.0f : INF;
        row_step(v0, v1, v2, v3, p0, p1, p2, p3, hl, hr,
                 aj0, aj1, aj2, aj3, ajL, ajR, lane, w, u & 1, sm_lb, sm_rb);
        float4 val = make_float4(p0, p1, p2, p3);
        *reinterpret_cast<float4*>(g_d + (size_t)b*NPIX + (RB*m+u)*WW + q0) = val;
        *reinterpret_cast<float4*>(&sbuf[u][q0]) = val;
    }
    __syncthreads();

    p0 = p1 = p2 = p3 = INF; hl = hr = INF;
    for (int u2 = 0; u2 < RB; u2++) {
        float4 a = *reinterpret_cast<const float4*>(&sbuf[RB-1-u2][WW-4-q0]);
        row_step(a.w, a.z, a.y, a.x, p0, p1, p2, p3, hl, hr,
                 aj0, aj1, aj2, aj3, ajL, ajR, lane, w, u2 & 1, sm_lb, sm_rb);
    }
    int band2 = MB - 1 - m;
    float4 val = make_float4(p0, p1, p2, p3);
    *reinterpret_cast<float4*>(g_lr2 + ((size_t)b*MB + band2)*WW + q0) = val;
    *reinterpret_cast<float4*>(g_bn2 + ((size_t)b*MB + band2)*WW + q0) = val;
}

// ---------------------------------------------------------------------------
__device__ __forceinline__ void loss_px(float x, float tv, float draw,
    float& fs, float& bA, float& bD, float& iS, float& pS, float& tS)
{
    float ax = fabsf(x);
    float ea = __expf(-ax);
    float den = 1.0f + ea;
    float rr = 1.0f / den;
    float pp = (x >= 0.f) ? rr : ea * rr;
    float ls = fminf(x, 0.f) - __logf(den);
    float bce = (1.f - tv) * x - ls;
    float pt  = (tv == 1.f) ? pp : 1.f - pp;
    float at  = (tv == 1.f) ? 0.25f : 0.75f;
    float omp = 1.f - pt;
    fs += at * omp * omp * bce;
    float base = tv * (1.f - pp) + (1.f - tv) * pp;
    bA += base;
    bD += base * draw;
    iS += pp * tv; pS += pp; tS += tv;
}

// Stage 5: phase C pass 2 with inline loss.
__global__ void __launch_bounds__(128, 1) kC2L(const float* __restrict__ pred) {
    __shared__ float sm_lb[2][4], sm_rb[2][4];
    __shared__ float red[4][6];
    const float A = 0.955f, INF = 1.0e6f;
    int m = blockIdx.x, b = blockIdx.y;
    int t = threadIdx.x, lane = t & 31, w = t >> 5;
    int q0 = 4 * t;
    const float aj0 = A*(float)q0,     aj1 = A*(float)(q0+1);
    const float aj2 = A*(float)(q0+2), aj3 = A*(float)(q0+3);
    const float ajL = A*(float)(q0-1), ajR = A*(float)(q0+4);
    size_t base = (size_t)b * NPIX;

    float p0 = INF, p1 = INF, p2 = INF, p3 = INF, hl = INF, hr = INF;
    if (m > 0)
        load_init(g_bn2 + ((size_t)b*MB + (m-1))*WW, q0, lane, p0, p1, p2, p3, hl, hr);

    const float* vbase = g_d + base;
    float4 nv  = *reinterpret_cast<const float4*>(vbase + (HH-1-RB*m)*WW + (WW-4-q0));
    float4 nv2 = *reinterpret_cast<const float4*>(vbase + (HH-2-RB*m)*WW + (WW-4-q0));

    float fs = 0.f, bA = 0.f, bD = 0.f, iS = 0.f, pS = 0.f, tS = 0.f;
    float mx = -1.0f;
    for (int u = 0; u < RB; u++) {
        int r  = RB*m + u;
        int pr = HH - 1 - r;
        float4 cu = nv; nv = nv2;
        if (u + 2 < RB)
            nv2 = *reinterpret_cast<const float4*>(vbase + (pr-2)*WW + (WW-4-q0));
        float4 xv = *reinterpret_cast<const float4*>(pred + base + pr*WW + (WW-4-q0));
        unsigned um = *reinterpret_cast<const unsigned*>(g_bmask + base + pr*WW + (WW-4-q0));

        row_step(cu.w, cu.z, cu.y, cu.x, p0, p1, p2, p3, hl, hr,
                 aj0, aj1, aj2, aj3, ajL, ajR, lane, w, u & 1, sm_lb, sm_rb);
        mx = fmaxf(fmaxf(mx, fmaxf(p0, p1)), fmaxf(p2, p3));

        loss_px(xv.x, (float)((um >> 1)  & 1u), p3, fs, bA, bD, iS, pS, tS);
        loss_px(xv.y, (float)((um >> 9)  & 1u), p2, fs, bA, bD, iS, pS, tS);
        loss_px(xv.z, (float)((um >> 17) & 1u), p1, fs, bA, bD, iS, pS, tS);
        loss_px(xv.w, (float)((um >> 25) & 1u), p0, fs, bA, bD, iS, pS, tS);
    }

    #pragma unroll
    for (int o = 16; o > 0; o >>= 1) {
        fs += __shfl_xor_sync(FULL, fs, o);
        bA += __shfl_xor_sync(FULL, bA, o);
        bD += __shfl_xor_sync(FULL, bD, o);
        iS += __shfl_xor_sync(FULL, iS, o);
        pS += __shfl_xor_sync(FULL, pS, o);
        tS += __shfl_xor_sync(FULL, tS, o);
        mx  = fmaxf(mx, __shfl_xor_sync(FULL, mx, o));
    }
    if (lane == 0) {
        red[w][0] = fs; red[w][1] = bA; red[w][2] = bD;
        red[w][3] = iS; red[w][4] = pS; red[w][5] = tS;
        atomicMax(&g_mxi[b], __float_as_int(mx));
    }
    __syncthreads();
    if (t == 0) {
        float a0=0,a1=0,a2=0,a3=0,a4=0,a5=0;
        #pragma unroll
        for (int ww = 0; ww < 4; ww++) {
            a0+=red[ww][0]; a1+=red[ww][1]; a2+=red[ww][2];
            a3+=red[ww][3]; a4+=red[ww][4]; a5+=red[ww][5];
        }
        atomicAdd(&g_acc[0], (double)a0);
        atomicAdd(&g_acc[1], (double)a1);
        atomicAdd(&g_acc[2 + b],        (double)a2);
        atomicAdd(&g_acc[2 + NB + b],   (double)a3);
        atomicAdd(&g_acc[2 + 2*NB + b], (double)a4);
        atomicAdd(&g_acc[2 + 3*NB + b], (double)a5);
    }
}

// ---------------------------------------------------------------------------
__global__ void k_final(const float* __restrict__ lv, float* __restrict__ out) {
    double N = (double)NB * (double)NPIX;
    double focal = g_acc[0] / N;
    double bndsum = g_acc[1];
    double ds = 0.0, us = 0.0;
    for (int b = 0; b < NB; b++) {
        double mx = (double)__int_as_float(g_mxi[b]);
        double dd = g_acc[2 + b];
        bndsum += (mx > 0.0) ? dd / mx : dd;
        double inter = g_acc[2 + NB + b];
        double tot   = g_acc[2 + 2*NB + b] + g_acc[2 + 3*NB + b];
        ds += (2.0*inter + 1e-6) / (tot + 1e-6);
        us += (inter + 1e-6) / (tot - inter + 1e-6);
    }
    double bnd  = bndsum / N;
    double dice = 1.0 - ds / NB;
    double iou  = 1.0 - us / NB;
    double l0 = lv[0], l1 = lv[1], l2 = lv[2], l3 = lv[3];
    double total = exp(-l0)*focal + l0 + exp(-l1)*dice + l1
                 + exp(-l2)*bnd + l2 + exp(-l3)*iou + l3;
    out[0] = (float)total;
    out[1] = (float)focal;
    out[2] = (float)dice;
    out[3] = (float)bnd;
    out[4] = (float)iou;
    for (int i = 0; i < 2 + 4*NB; i++) g_acc[i] = 0.0;
    for (int i = 0; i < NB; i++) g_mxi[i] = 0;
}

// ---------------------------------------------------------------------------
extern "C" void kernel_launch(void* const* d_in, const int* in_sizes, int n_in,
                              void* d_out, int out_size) {
    const float* pred = (const float*)d_in[0];
    const int*   tgt  = (const int*)d_in[1];
    const float* lv   = (const float*)d_in[2];
    float* out = (float*)d_out;

    kA1<<<dim3(MB, NB), 128>>>(tgt);
    k_conv<1><<<dim3(MB-1, 8, NB), 128>>>();
    kC1A2<<<dim3(MB, NB), 128>>>();
    k_conv<2><<<dim3(MB-1, 8, NB), 128>>>();
    kC2L<<<dim3(MB, NB), 128>>>(pred);
    k_final<<<1, 1>>>(lv, out);
}